// round 8
// baseline (speedup 1.0000x reference)
#include <cuda_runtime.h>
#include <cuda_bf16.h>

#define NN 100000
#define NE_MAX 1600000
#define INC 64
#define HIDC 128
#define OUTC 64
#define NCLS 20
#define NCHUNK 98          // ceil(NN/1024)

typedef unsigned long long ull;

// ---------------- device scratch (static globals; no allocation) ------------
__device__ int   g_is64;
__device__ __align__(16) int2 g_edges[NE_MAX];
__device__ int   g_degi[NN];
__device__ int   g_rowstart[NN];
__device__ int   g_cursor[NN];
__device__ int   g_srclist[NE_MAX];
__device__ int   g_chunksum[NCHUNK];
__device__ int   g_chunkoff[NCHUNK];
__device__ float g_dinv[NN];
__device__ __align__(16) float g_agg1[(size_t)NN * INC];
__device__ __align__(16) float g_h1[(size_t)NN * HIDC];
__device__ __align__(16) float g_p[(size_t)NN * OUTC];
__device__ __align__(16) float g_s2[(size_t)NN * OUTC];
__device__ __align__(16) float g_h2[(size_t)NN * OUTC];

// packed f32x2 FMA: acc.(lo,hi) += a.(lo,hi) * b.(lo,hi)
__device__ __forceinline__ void fma2(ull& acc, ull a, ull b) {
    asm("fma.rn.f32x2 %0, %1, %2, %0;" : "+l"(acc) : "l"(a), "l"(b));
}
__device__ __forceinline__ float fold2(ull v) {
    return __uint_as_float((unsigned)v) + __uint_as_float((unsigned)(v >> 32));
}

// ---------------- CSR build kernels -----------------------------------------

__global__ void k_detect(const int* __restrict__ ei32, int n32, int* __restrict__ flag) {
    __shared__ int s_any;
    if (threadIdx.x == 0) s_any = 0;
    __syncthreads();
    int nonzero = 0;
    int limit = n32 < 16384 ? n32 : 16384;
    for (int i = 1 + 2 * threadIdx.x; i < limit; i += 2 * blockDim.x)
        if (ei32[i] != 0) nonzero = 1;
    if (nonzero) atomicOr(&s_any, 1);
    __syncthreads();
    if (threadIdx.x == 0) *flag = (s_any == 0) ? 1 : 0;  // all-zero odd words -> int64
}

__global__ void k_zero_deg(int* __restrict__ degi) {
    int i = blockIdx.x * blockDim.x + threadIdx.x;
    if (i < NN) degi[i] = 0;
}

__global__ void k_convert(const void* __restrict__ ei, int nE, int2* __restrict__ edges,
                          int* __restrict__ degi, const int* __restrict__ flag) {
    int e = blockIdx.x * blockDim.x + threadIdx.x;
    if (e >= nE) return;
    int s, d;
    if (*flag) {
        s = (int)((const long long*)ei)[e];
        d = (int)((const long long*)ei)[(long long)nE + e];
    } else {
        s = ((const int*)ei)[e];
        d = ((const int*)ei)[nE + e];
    }
    if ((unsigned)s >= NN) s = 0;
    if ((unsigned)d >= NN) d = 0;
    edges[e] = make_int2(s, d);
    atomicAdd(&degi[d], 1);
}

__global__ __launch_bounds__(1024) void k_scanA(const int* __restrict__ degi,
                                                int* __restrict__ chunksum) {
    __shared__ int s[1024];
    int i = blockIdx.x * 1024 + threadIdx.x;
    s[threadIdx.x] = (i < NN) ? degi[i] : 0;
    __syncthreads();
    for (int off = 512; off > 0; off >>= 1) {
        if (threadIdx.x < off) s[threadIdx.x] += s[threadIdx.x + off];
        __syncthreads();
    }
    if (threadIdx.x == 0) chunksum[blockIdx.x] = s[0];
}

__global__ void k_scanB(const int* __restrict__ chunksum, int* __restrict__ chunkoff) {
    __shared__ int s[128];
    int v = (threadIdx.x < NCHUNK) ? chunksum[threadIdx.x] : 0;
    s[threadIdx.x] = v;
    __syncthreads();
    for (int off = 1; off < 128; off <<= 1) {
        int t = (threadIdx.x >= off) ? s[threadIdx.x - off] : 0;
        __syncthreads();
        s[threadIdx.x] += t;
        __syncthreads();
    }
    if (threadIdx.x < NCHUNK) chunkoff[threadIdx.x] = s[threadIdx.x] - v;
}

__global__ __launch_bounds__(1024) void k_scanC(const int* __restrict__ degi,
                                                const int* __restrict__ chunkoff,
                                                int* __restrict__ rowstart,
                                                int* __restrict__ cursor,
                                                float* __restrict__ dinv) {
    __shared__ int s[1024];
    int i = blockIdx.x * 1024 + threadIdx.x;
    int v = (i < NN) ? degi[i] : 0;
    s[threadIdx.x] = v;
    __syncthreads();
    for (int off = 1; off < 1024; off <<= 1) {
        int t = (threadIdx.x >= off) ? s[threadIdx.x - off] : 0;
        __syncthreads();
        s[threadIdx.x] += t;
        __syncthreads();
    }
    if (i < NN) {
        int excl = s[threadIdx.x] - v + chunkoff[blockIdx.x];
        rowstart[i] = excl;
        cursor[i] = excl;
        dinv[i] = 1.0f / fmaxf((float)v, 1.0f);
    }
}

__global__ void k_scatter(const int2* __restrict__ edges, int nE,
                          int* __restrict__ cursor, int* __restrict__ srclist) {
    int e = blockIdx.x * blockDim.x + threadIdx.x;
    if (e >= nE) return;
    int2 ed = edges[e];
    int p = atomicAdd(&cursor[ed.y], 1);
    srclist[p] = ed.x;
}

// ---------------- gather kernels ---------------------------------------------

__global__ __launch_bounds__(256) void k_gather1(
    const float4* __restrict__ feat, const int* __restrict__ rowstart,
    const int* __restrict__ degi, const int* __restrict__ srclist,
    const float* __restrict__ dinv, float4* __restrict__ out) {
    int node = blockIdx.x * 8 + (threadIdx.x >> 5);
    if (node >= NN) return;
    int lane = threadIdx.x & 31;
    int half = lane >> 4;
    int c = lane & 15;
    int beg = rowstart[node];
    int cnt = degi[node];
    float4 acc = make_float4(0.f, 0.f, 0.f, 0.f);
    for (int i = half; i < cnt; i += 2) {
        int s = __ldg(&srclist[beg + i]);
        float4 v = __ldg(&feat[(long long)s * 16 + c]);
        acc.x += v.x; acc.y += v.y; acc.z += v.z; acc.w += v.w;
    }
    acc.x += __shfl_xor_sync(0xffffffffu, acc.x, 16);
    acc.y += __shfl_xor_sync(0xffffffffu, acc.y, 16);
    acc.z += __shfl_xor_sync(0xffffffffu, acc.z, 16);
    acc.w += __shfl_xor_sync(0xffffffffu, acc.w, 16);
    if (half == 0) {
        float di = dinv[node];
        out[(long long)node * 16 + c] =
            make_float4(acc.x * di, acc.y * di, acc.z * di, acc.w * di);
    }
}

__global__ __launch_bounds__(256) void k_gather2(
    const float4* __restrict__ pfeat, const int* __restrict__ rowstart,
    const int* __restrict__ degi, const int* __restrict__ srclist,
    const float* __restrict__ dinv, const float4* __restrict__ s2,
    const float4* __restrict__ b2, float4* __restrict__ h2) {
    int node = blockIdx.x * 8 + (threadIdx.x >> 5);
    if (node >= NN) return;
    int lane = threadIdx.x & 31;
    int half = lane >> 4;
    int c = lane & 15;
    int beg = rowstart[node];
    int cnt = degi[node];
    float4 acc = make_float4(0.f, 0.f, 0.f, 0.f);
    for (int i = half; i < cnt; i += 2) {
        int s = __ldg(&srclist[beg + i]);
        float4 v = __ldg(&pfeat[(long long)s * 16 + c]);
        acc.x += v.x; acc.y += v.y; acc.z += v.z; acc.w += v.w;
    }
    acc.x += __shfl_xor_sync(0xffffffffu, acc.x, 16);
    acc.y += __shfl_xor_sync(0xffffffffu, acc.y, 16);
    acc.z += __shfl_xor_sync(0xffffffffu, acc.z, 16);
    acc.w += __shfl_xor_sync(0xffffffffu, acc.w, 16);
    if (half == 0) {
        float di = dinv[node];
        float4 sv = __ldg(&s2[(long long)node * 16 + c]);
        float4 bv = __ldg(&b2[c]);
        float4 r;
        r.x = fmaxf(sv.x + acc.x * di + bv.x, 0.f);
        r.y = fmaxf(sv.y + acc.y * di + bv.y, 0.f);
        r.z = fmaxf(sv.z + acc.z * di + bv.z, 0.f);
        r.w = fmaxf(sv.w + acc.w * di + bv.w, 0.f);
        h2[(long long)node * 16 + c] = r;
    }
}

// ---------------- GEMM kernels (f32x2 packed FMA) ----------------------------
// Pair dimension = k: acc pair holds (even-k, odd-k) partial sums, folded at end.
// sWp[k2*128 + j] = (W[2k2][j], W[2k2+1][j]) packed as f32x2 in a ull.

// layer1: h1 = relu(x@Ws + agg@Wn + b). 32 nodes/block, 128 threads.
// Thread: 4 cols (j0=lane*4) x 8 nodes (warp -> node group). K=64 -> 32 k2.
__global__ __launch_bounds__(128) void k_layer1(
    const float* __restrict__ x, const float* __restrict__ agg,
    const float* __restrict__ Wself, const float* __restrict__ Wneigh,
    const float* __restrict__ b, float* __restrict__ h1) {
    __shared__ ull   sWp[32 * HIDC];   // 32 KB packed weight pairs
    __shared__ float sF[32 * INC];     // 8 KB features
    const int tid = threadIdx.x;
    const int lane = tid & 31;
    const int wrp = tid >> 5;
    const int j0 = lane * 4;
    const int nb = wrp * 8;
    const int n0 = blockIdx.x * 32;

    ull acc[8][4];
#pragma unroll
    for (int n = 0; n < 8; n++)
#pragma unroll
        for (int j = 0; j < 4; j++) acc[n][j] = 0ull;

#pragma unroll
    for (int pass = 0; pass < 2; pass++) {
        const float* W = pass ? Wneigh : Wself;
        const float* F = pass ? agg : x;
        if (pass) __syncthreads();
        // pack weight pairs: i -> (k2 = i>>7, j = i&127)
        for (int i = tid; i < 32 * HIDC; i += 128) {
            int k2 = i >> 7, j = i & 127;
            float lo = W[(2 * k2) * HIDC + j];
            float hi = W[(2 * k2 + 1) * HIDC + j];
            ull v = (ull)__float_as_uint(lo) | ((ull)__float_as_uint(hi) << 32);
            sWp[i] = v;
        }
        {
            const float4* fr = (const float4*)(F + (long long)n0 * INC);
            for (int i = tid; i < 32 * INC / 4; i += 128) ((float4*)sF)[i] = fr[i];
        }
        __syncthreads();
#pragma unroll 4
        for (int k4 = 0; k4 < 16; k4++) {        // k4 covers k2 = 2k4, 2k4+1
            ulonglong2 wA = *(const ulonglong2*)&sWp[(2 * k4) * HIDC + j0];
            ulonglong2 wA2 = *(const ulonglong2*)&sWp[(2 * k4) * HIDC + j0 + 2];
            ulonglong2 wB = *(const ulonglong2*)&sWp[(2 * k4 + 1) * HIDC + j0];
            ulonglong2 wB2 = *(const ulonglong2*)&sWp[(2 * k4 + 1) * HIDC + j0 + 2];
#pragma unroll
            for (int n = 0; n < 8; n++) {
                ulonglong2 f = *(const ulonglong2*)&sF[(nb + n) * INC + k4 * 4];
                fma2(acc[n][0], f.x, wA.x);
                fma2(acc[n][1], f.x, wA.y);
                fma2(acc[n][2], f.x, wA2.x);
                fma2(acc[n][3], f.x, wA2.y);
                fma2(acc[n][0], f.y, wB.x);
                fma2(acc[n][1], f.y, wB.y);
                fma2(acc[n][2], f.y, wB2.x);
                fma2(acc[n][3], f.y, wB2.y);
            }
        }
    }
    float4 bv = *(const float4*)&b[j0];
#pragma unroll
    for (int n = 0; n < 8; n++) {
        float4 r;
        r.x = fmaxf(fold2(acc[n][0]) + bv.x, 0.f);
        r.y = fmaxf(fold2(acc[n][1]) + bv.y, 0.f);
        r.z = fmaxf(fold2(acc[n][2]) + bv.z, 0.f);
        r.w = fmaxf(fold2(acc[n][3]) + bv.w, 0.f);
        *(float4*)&h1[((long long)(n0 + nb + n)) * HIDC + j0] = r;
    }
}

// dual GEMM: s2 = h1@Ws2, p = h1@Wn2. 128 virtual cols = [S 0..63 | P 64..127].
// K=128 in two 64-k passes; same f32x2 scheme.
__global__ __launch_bounds__(128) void k_dual(
    const float* __restrict__ h1,
    const float* __restrict__ Wself2, const float* __restrict__ Wneigh2,
    float* __restrict__ s2, float* __restrict__ p) {
    __shared__ ull   sWp[32 * 128];    // 32 KB packed pairs for current k-slice
    __shared__ float sF[32 * 64];      // 8 KB
    const int tid = threadIdx.x;
    const int lane = tid & 31;
    const int wrp = tid >> 5;
    const int j0 = lane * 4;           // virtual col group (same matrix)
    const int nb = wrp * 8;
    const int n0 = blockIdx.x * 32;

    ull acc[8][4];
#pragma unroll
    for (int n = 0; n < 8; n++)
#pragma unroll
        for (int j = 0; j < 4; j++) acc[n][j] = 0ull;

#pragma unroll
    for (int kp = 0; kp < 2; kp++) {
        if (kp) __syncthreads();
        for (int i = tid; i < 32 * 128; i += 128) {
            int k2 = i >> 7, jv = i & 127;
            const float* W = (jv < 64) ? Wself2 : Wneigh2;
            int jd = jv & 63;
            float lo = W[(kp * 64 + 2 * k2) * OUTC + jd];
            float hi = W[(kp * 64 + 2 * k2 + 1) * OUTC + jd];
            sWp[i] = (ull)__float_as_uint(lo) | ((ull)__float_as_uint(hi) << 32);
        }
        for (int i = tid * 4; i < 32 * 64; i += 128 * 4) {
            int n = i >> 6, kk = i & 63;
            *(float4*)&sF[i] = *(const float4*)&h1[((long long)(n0 + n)) * HIDC + kp * 64 + kk];
        }
        __syncthreads();
#pragma unroll 4
        for (int k4 = 0; k4 < 16; k4++) {
            ulonglong2 wA = *(const ulonglong2*)&sWp[(2 * k4) * 128 + j0];
            ulonglong2 wA2 = *(const ulonglong2*)&sWp[(2 * k4) * 128 + j0 + 2];
            ulonglong2 wB = *(const ulonglong2*)&sWp[(2 * k4 + 1) * 128 + j0];
            ulonglong2 wB2 = *(const ulonglong2*)&sWp[(2 * k4 + 1) * 128 + j0 + 2];
#pragma unroll
            for (int n = 0; n < 8; n++) {
                ulonglong2 f = *(const ulonglong2*)&sF[(nb + n) * 64 + k4 * 4];
                fma2(acc[n][0], f.x, wA.x);
                fma2(acc[n][1], f.x, wA.y);
                fma2(acc[n][2], f.x, wA2.x);
                fma2(acc[n][3], f.x, wA2.y);
                fma2(acc[n][0], f.y, wB.x);
                fma2(acc[n][1], f.y, wB.y);
                fma2(acc[n][2], f.y, wB2.x);
                fma2(acc[n][3], f.y, wB2.y);
            }
        }
    }
    float* dst = (j0 < 64) ? s2 : p;
    int jd = j0 & 63;
#pragma unroll
    for (int n = 0; n < 8; n++) {
        float4 r;
        r.x = fold2(acc[n][0]);
        r.y = fold2(acc[n][1]);
        r.z = fold2(acc[n][2]);
        r.w = fold2(acc[n][3]);
        *(float4*)&dst[((long long)(n0 + nb + n)) * OUTC + jd] = r;
    }
}

// classifier: out = h2 @ wc + bc
__global__ __launch_bounds__(256) void k_out(const float* __restrict__ h2,
                                             const float* __restrict__ wc,
                                             const float* __restrict__ bc,
                                             float* __restrict__ out) {
    __shared__ float sW[OUTC * NCLS];
    __shared__ float sB[NCLS];
    __shared__ float sH[12 * 65];
    const int tid = threadIdx.x;
    const int n0 = blockIdx.x * 12;
    const int nmax = min(12, NN - n0);
    for (int i = tid; i < OUTC * NCLS; i += 256) sW[i] = wc[i];
    if (tid < NCLS) sB[tid] = bc[tid];
    for (int i = tid; i < nmax * OUTC; i += 256) {
        int ln = i >> 6, k = i & 63;
        sH[ln * 65 + k] = h2[(long long)(n0 + ln) * OUTC + k];
    }
    __syncthreads();
    if (tid < 240) {
        int ln = tid / 20, c = tid % 20;
        if (ln < nmax) {
            float acc = sB[c];
#pragma unroll
            for (int k = 0; k < OUTC; k++)
                acc = fmaf(sH[ln * 65 + k], sW[k * NCLS + c], acc);
            out[(long long)(n0 + ln) * NCLS + c] = acc;
        }
    }
}

// ---------------- launch ----------------------------------------------------
extern "C" void kernel_launch(void* const* d_in, const int* in_sizes, int n_in,
                              void* d_out, int out_size) {
    const float* x   = (const float*)d_in[0];
    const void*  ei  = d_in[1];
    const float* ws1 = (const float*)d_in[2];
    const float* wn1 = (const float*)d_in[3];
    const float* b1  = (const float*)d_in[4];
    const float* ws2 = (const float*)d_in[5];
    const float* wn2 = (const float*)d_in[6];
    const float* b2  = (const float*)d_in[7];
    const float* wc  = (const float*)d_in[8];
    const float* bc  = (const float*)d_in[9];
    float* out = (float*)d_out;

    int nE = in_sizes[1] / 2;
    if (nE > NE_MAX) nE = NE_MAX;

    void *p_flag, *p_edges, *p_degi, *p_rs, *p_cur, *p_src, *p_cs, *p_co;
    void *p_dinv, *p_agg1, *p_h1, *p_pp, *p_s2, *p_h2;
    cudaGetSymbolAddress(&p_flag, g_is64);
    cudaGetSymbolAddress(&p_edges, g_edges);
    cudaGetSymbolAddress(&p_degi, g_degi);
    cudaGetSymbolAddress(&p_rs,   g_rowstart);
    cudaGetSymbolAddress(&p_cur,  g_cursor);
    cudaGetSymbolAddress(&p_src,  g_srclist);
    cudaGetSymbolAddress(&p_cs,   g_chunksum);
    cudaGetSymbolAddress(&p_co,   g_chunkoff);
    cudaGetSymbolAddress(&p_dinv, g_dinv);
    cudaGetSymbolAddress(&p_agg1, g_agg1);
    cudaGetSymbolAddress(&p_h1,   g_h1);
    cudaGetSymbolAddress(&p_pp,   g_p);
    cudaGetSymbolAddress(&p_s2,   g_s2);
    cudaGetSymbolAddress(&p_h2,   g_h2);
    int*   flag  = (int*)p_flag;
    int2*  edges = (int2*)p_edges;
    int*   degi  = (int*)p_degi;
    int*   rs    = (int*)p_rs;
    int*   cur   = (int*)p_cur;
    int*   src   = (int*)p_src;
    int*   cs    = (int*)p_cs;
    int*   co    = (int*)p_co;
    float* dinv  = (float*)p_dinv;
    float* agg1  = (float*)p_agg1;
    float* h1    = (float*)p_h1;
    float* pp    = (float*)p_pp;
    float* s2    = (float*)p_s2;
    float* h2    = (float*)p_h2;

    // dtype detect + CSR build
    k_detect<<<1, 256>>>((const int*)ei, in_sizes[1], flag);
    k_zero_deg<<<(NN + 255) / 256, 256>>>(degi);
    k_convert<<<(nE + 255) / 256, 256>>>(ei, nE, edges, degi, flag);
    k_scanA<<<NCHUNK, 1024>>>(degi, cs);
    k_scanB<<<1, 128>>>(cs, co);
    k_scanC<<<NCHUNK, 1024>>>(degi, co, rs, cur, dinv);
    k_scatter<<<(nE + 255) / 256, 256>>>(edges, nE, cur, src);

    // layer 1
    k_gather1<<<(NN + 7) / 8, 256>>>((const float4*)x, rs, degi, src, dinv,
                                     (float4*)agg1);
    k_layer1<<<NN / 32, 128>>>(x, agg1, ws1, wn1, b1, h1);

    // layer 2
    k_dual<<<NN / 32, 128>>>(h1, ws2, wn2, s2, pp);
    k_gather2<<<(NN + 7) / 8, 256>>>((const float4*)pp, rs, degi, src, dinv,
                                     (const float4*)s2, (const float4*)b2,
                                     (float4*)h2);

    // classifier
    k_out<<<(NN + 11) / 12, 256>>>(h2, wc, bc, out);
}